// round 7
// baseline (speedup 1.0000x reference)
#include <cuda_runtime.h>
#include <cuda_bf16.h>
#include <cuda_fp16.h>

// ---------------------------------------------------------------------------
// Simplex4Net: B=32, N=64, D=64
//   kA: projections (+ zero the completion counter)
//   kB: six Gram matrices * 0.0625
//   kC: main B*N^4 loop. Energy math in f16x2 (HADD2 + tanh.approx.f16x2,
//       halving MUFU), det/acc in f32x2. Gate split: sigma(E)det^2 =
//       0.5 det^2 (closed form via S) + 0.5 det^2 tanh(E/2).
//       Last block (atomic counter) performs the mean + gelu MLP head.
// ---------------------------------------------------------------------------

#define BSZ 32
#define NP  64
#define DD  64

__device__ float g_K[4][BSZ][NP * DD];
__device__ float g_E[6][BSZ][NP * NP];   // 0:(i,j) 1:(i,k) 2:(i,l) 3:(j,k) 4:(j,l) 5:(l,k)^T
__device__ float g_anchor[BSZ * NP];
__device__ unsigned g_done;

typedef unsigned long long ull;

__device__ __forceinline__ ull pk2(float lo, float hi) {
    ull r; asm("mov.b64 %0, {%1, %2};" : "=l"(r) : "f"(lo), "f"(hi)); return r;
}
__device__ __forceinline__ void upk2(ull v, float& lo, float& hi) {
    asm("mov.b64 {%0, %1}, %2;" : "=f"(lo), "=f"(hi) : "l"(v));
}
__device__ __forceinline__ ull add2(ull a, ull b) {
    ull r; asm("add.rn.f32x2 %0, %1, %2;" : "=l"(r) : "l"(a), "l"(b)); return r;
}
__device__ __forceinline__ ull mul2(ull a, ull b) {
    ull r; asm("mul.rn.f32x2 %0, %1, %2;" : "=l"(r) : "l"(a), "l"(b)); return r;
}
__device__ __forceinline__ ull fma2(ull a, ull b, ull c) {
    ull r; asm("fma.rn.f32x2 %0, %1, %2, %3;" : "=l"(r) : "l"(a), "l"(b), "l"(c)); return r;
}
__device__ __forceinline__ __half2 tanh2h(__half2 x) {
    unsigned xu = *reinterpret_cast<unsigned*>(&x);
    unsigned yu;
    asm("tanh.approx.f16x2 %0, %1;" : "=r"(yu) : "r"(xu));
    return *reinterpret_cast<__half2*>(&yu);
}

// ---------------------------------------------------------------------------
__global__ void kA(const float* __restrict__ pc,
                   const float* __restrict__ Wq,  const float* __restrict__ bq,
                   const float* __restrict__ Wk1, const float* __restrict__ bk1,
                   const float* __restrict__ Wk2, const float* __restrict__ bk2,
                   const float* __restrict__ Wk3, const float* __restrict__ bk3)
{
    int b = blockIdx.x;
    __shared__ float sp[NP * 3];
    __shared__ float sW[4][3 * DD];
    __shared__ float sb[4][DD];
    int t = threadIdx.x;
    if (b == 0 && t == 0) g_done = 0;        // reset fused-head counter
    if (t < 192) {
        sp[t]    = pc[b * 192 + t];
        sW[0][t] = Wq[t];
        sW[1][t] = Wk1[t];
        sW[2][t] = Wk2[t];
        sW[3][t] = Wk3[t];
    }
    if (t < 64) {
        sb[0][t] = bq[t]; sb[1][t] = bk1[t]; sb[2][t] = bk2[t]; sb[3][t] = bk3[t];
    }
    __syncthreads();
    for (int m = 0; m < 4; m++) {
        const float* W = sW[m];
        const float* bb = sb[m];
        for (int idx = t; idx < NP * DD; idx += 256) {
            int n = idx >> 6, d = idx & 63;
            float v = bb[d]
                    + sp[n * 3 + 0] * W[d]
                    + sp[n * 3 + 1] * W[64 + d]
                    + sp[n * 3 + 2] * W[128 + d];
            g_K[m][b][idx] = v;
        }
    }
}

// ---------------------------------------------------------------------------
__global__ void kB()
{
    int p = blockIdx.x, b = blockIdx.y;
    const int XI[6] = {0, 0, 0, 1, 1, 3};
    const int YI[6] = {1, 2, 3, 2, 3, 2};
    __shared__ float sX[NP][65];
    __shared__ float sY[NP][65];
    int t = threadIdx.x;
    const float* X = g_K[XI[p]][b];
    const float* Y = g_K[YI[p]][b];
    for (int idx = t; idx < NP * DD; idx += 256) {
        sX[idx >> 6][idx & 63] = X[idx];
        sY[idx >> 6][idx & 63] = Y[idx];
    }
    __syncthreads();
    for (int idx = t; idx < NP * NP; idx += 256) {
        int n = idx >> 6, m = idx & 63;
        float s = 0.f;
        #pragma unroll
        for (int d = 0; d < DD; d++)
            s = fmaf(sX[n][d], sY[m][d], s);
        g_E[p][b][idx] = s * 0.0625f;
    }
}

// ---------------------------------------------------------------------------
// Kernel C: grid=(i=64,b=32), 256 threads, occ-3 via smem pad.
// Thread = (k = t&63, l-quad per unit); jp loop covers 2 j's, f16 energies.
// ---------------------------------------------------------------------------
__global__ void __launch_bounds__(256, 3) kC(const float* __restrict__ pc,
                                             const float* __restrict__ W1,
                                             const float* __restrict__ b1,
                                             const float* __restrict__ W2,
                                             const float* __restrict__ b2,
                                             float* __restrict__ out)
{
    __shared__ __half2 SA2h[64 * 64];        // 16 KB  {a,a} per (j,k)
    __shared__ __half  SB4h[64 * 64];        // 8 KB   b per (j,l)
    __shared__ ull     DJ[32][6];            // 1.5 KB
    __shared__ float4  dS[NP];               // 1 KB
    __shared__ float   ekA[NP];
    __shared__ float   sS[6];
    __shared__ float   red[8];
    __shared__ float   sbat[BSZ];
    __shared__ int     sflag;
    __shared__ ull     PAD[4096];            // 32 KB -> ~59KB total -> occ 3

    int i = blockIdx.x, b = blockIdx.y, t = threadIdx.x;
    if (pc == (const float*)1) ((volatile ull*)PAD)[0] = 1;   // keep PAD live

    const float* E0r = &g_E[0][b][i * 64];
    const float* E2r = &g_E[2][b][i * 64];
    const float* E3b = g_E[3][b];
    const float* E4b = g_E[4][b];

    for (int idx = t; idx < NP * NP; idx += 256) {
        int j = idx >> 6, c = idx & 63;
        float av = E3b[idx] + E0r[j];
        SA2h[(j << 6) + c] = __float2half2_rn(av);
        float bv = E4b[idx] + E2r[c];
        SB4h[(j << 6) + c] = __float2half_rn(bv);
    }
    if (t < 64) {
        ekA[t] = g_E[1][b][i * 64 + t];
        float ix = pc[b * 192 + i * 3 + 0];
        float iy = pc[b * 192 + i * 3 + 1];
        float iz = pc[b * 192 + i * 3 + 2];
        float dx = pc[b * 192 + t * 3 + 0] - ix;
        float dy = pc[b * 192 + t * 3 + 1] - iy;
        float dz = pc[b * 192 + t * 3 + 2] - iz;
        dS[t] = make_float4(dx, dy, dz, 0.f);
    }
    __syncthreads();
    if (t < 32) {
        float4 d0 = dS[2 * t], d1 = dS[2 * t + 1];
        DJ[t][0] = pk2(d0.x, d0.x);
        DJ[t][1] = pk2(d0.y, d0.y);
        DJ[t][2] = pk2(d0.z, d0.z);
        DJ[t][3] = pk2(d1.x, d1.x);
        DJ[t][4] = pk2(d1.y, d1.y);
        DJ[t][5] = pk2(d1.z, d1.z);
    } else if (t < 38) {
        int e = t - 32;
        int c1 = 0, c2 = 0;
        if (e == 0) { c1 = 0; c2 = 0; }
        if (e == 1) { c1 = 1; c2 = 1; }
        if (e == 2) { c1 = 2; c2 = 2; }
        if (e == 3) { c1 = 0; c2 = 1; }
        if (e == 4) { c1 = 0; c2 = 2; }
        if (e == 5) { c1 = 1; c2 = 2; }
        float s = 0.f;
        for (int j = 0; j < 64; j++) {
            const float* dp = reinterpret_cast<const float*>(&dS[j]);
            s = fmaf(dp[c1], dp[c2], s);
        }
        sS[e] = s;
    }
    __syncthreads();

    const float* E5b = g_E[5][b];            // [l][k]
    ull accP = pk2(0.f, 0.f);
    ull accQ = pk2(0.f, 0.f);
    float qsum = 0.f;

    int k = t & 63;
    float4 dk = dS[k];
    float ekk = ekA[k];
    float Sxx = sS[0], Syy = sS[1], Szz = sS[2];
    float Sxy2 = 2.f * sS[3], Sxz2 = 2.f * sS[4], Syz2 = 2.f * sS[5];

    #pragma unroll 1
    for (int u = 0; u < 4; u++) {
        int lq = u * 4 + (t >> 6);
        int l0 = lq * 4;

        float4 dA = dS[l0 + 0];
        float4 dB = dS[l0 + 1];
        float4 dC = dS[l0 + 2];
        float4 dD = dS[l0 + 3];

        float cAx = dk.y * dA.z - dk.z * dA.y, cAy = dk.z * dA.x - dk.x * dA.z, cAz = dk.x * dA.y - dk.y * dA.x;
        float cBx = dk.y * dB.z - dk.z * dB.y, cBy = dk.z * dB.x - dk.x * dB.z, cBz = dk.x * dB.y - dk.y * dB.x;
        float cCx = dk.y * dC.z - dk.z * dC.y, cCy = dk.z * dC.x - dk.x * dC.z, cCz = dk.x * dC.y - dk.y * dC.x;
        float cDx = dk.y * dD.z - dk.z * dD.y, cDy = dk.z * dD.x - dk.x * dD.z, cDz = dk.x * dD.y - dk.y * dD.x;

        // closed-form ungated part: c^T S c per l
        {
            float qA = cAx * (fmaf(Sxy2, cAy, fmaf(Sxz2, cAz, Sxx * cAx)))
                     + cAy * fmaf(Syz2, cAz, Syy * cAy) + cAz * cAz * Szz;
            float qB = cBx * (fmaf(Sxy2, cBy, fmaf(Sxz2, cBz, Sxx * cBx)))
                     + cBy * fmaf(Syz2, cBz, Syy * cBy) + cBz * cBz * Szz;
            float qC = cCx * (fmaf(Sxy2, cCy, fmaf(Sxz2, cCz, Sxx * cCx)))
                     + cCy * fmaf(Syz2, cCz, Syy * cCy) + cCz * cCz * Szz;
            float qD = cDx * (fmaf(Sxy2, cDy, fmaf(Sxz2, cDz, Sxx * cDx)))
                     + cDy * fmaf(Syz2, cDz, Syy * cDy) + cDz * cDz * Szz;
            qsum += (qA + qB) + (qC + qD);
        }

        ull cx01 = pk2(cAx, cBx), cy01 = pk2(cAy, cBy), cz01 = pk2(cAz, cBz);
        ull cx23 = pk2(cCx, cDx), cy23 = pk2(cCy, cDy), cz23 = pk2(cCz, cDz);

        __half2 ecAh = __floats2half2_rn(ekk + E5b[(l0 + 0) * 64 + k], ekk + E5b[(l0 + 1) * 64 + k]);
        __half2 ecBh = __floats2half2_rn(ekk + E5b[(l0 + 2) * 64 + k], ekk + E5b[(l0 + 3) * 64 + k]);

        const __half* SBbase = SB4h + (lq << 2);

        #pragma unroll 4
        for (int jp = 0; jp < 32; jp++) {
            __half2 aa0 = SA2h[((2 * jp) << 6) + k];          // LDS.32, conflict-free
            __half2 aa1 = SA2h[((2 * jp + 1) << 6) + k];
            uint2 bq0 = *reinterpret_cast<const uint2*>(SBbase + ((2 * jp) << 6));      // broadcast
            uint2 bq1 = *reinterpret_cast<const uint2*>(SBbase + ((2 * jp + 1) << 6));
            ulonglong2 dxy0 = *reinterpret_cast<const ulonglong2*>(&DJ[jp][0]);
            ulonglong2 dzx1 = *reinterpret_cast<const ulonglong2*>(&DJ[jp][2]);
            ulonglong2 dyz1 = *reinterpret_cast<const ulonglong2*>(&DJ[jp][4]);

            // ---- j0 = 2jp ----
            {
                __half2 b01 = *reinterpret_cast<__half2*>(&bq0.x);
                __half2 b23 = *reinterpret_cast<__half2*>(&bq0.y);
                __half2 e01 = __hadd2(__hadd2(aa0, b01), ecAh);
                __half2 e23 = __hadd2(__hadd2(aa0, b23), ecBh);
                __half2 t01 = tanh2h(e01);
                __half2 t23 = tanh2h(e23);
                ull detP = fma2(cx01, dxy0.x, fma2(cy01, dxy0.y, mul2(cz01, dzx1.x)));
                ull detQ = fma2(cx23, dxy0.x, fma2(cy23, dxy0.y, mul2(cz23, dzx1.x)));
                ull ddP = mul2(detP, detP);
                ull ddQ = mul2(detQ, detQ);
                ull gP = pk2(__low2float(t01), __high2float(t01));
                ull gQ = pk2(__low2float(t23), __high2float(t23));
                accP = fma2(ddP, gP, accP);
                accQ = fma2(ddQ, gQ, accQ);
            }
            // ---- j1 = 2jp+1 ----
            {
                __half2 b01 = *reinterpret_cast<__half2*>(&bq1.x);
                __half2 b23 = *reinterpret_cast<__half2*>(&bq1.y);
                __half2 e01 = __hadd2(__hadd2(aa1, b01), ecAh);
                __half2 e23 = __hadd2(__hadd2(aa1, b23), ecBh);
                __half2 t01 = tanh2h(e01);
                __half2 t23 = tanh2h(e23);
                ull detP = fma2(cx01, dzx1.y, fma2(cy01, dyz1.x, mul2(cz01, dyz1.y)));
                ull detQ = fma2(cx23, dzx1.y, fma2(cy23, dyz1.x, mul2(cz23, dyz1.y)));
                ull ddP = mul2(detP, detP);
                ull ddQ = mul2(detQ, detQ);
                ull gP = pk2(__low2float(t01), __high2float(t01));
                ull gQ = pk2(__low2float(t23), __high2float(t23));
                accP = fma2(ddP, gP, accP);
                accQ = fma2(ddQ, gQ, accQ);
            }
        }
    }

    float a0, a1, b0_, b1_;
    upk2(accP, a0, a1); upk2(accQ, b0_, b1_);
    float v = ((a0 + a1) + (b0_ + b1_)) + qsum;
    #pragma unroll
    for (int off = 16; off > 0; off >>= 1)
        v += __shfl_xor_sync(0xFFFFFFFFu, v, off);
    if ((t & 31) == 0) red[t >> 5] = v;
    __syncthreads();
    if (t == 0) {
        float s = 0.f;
        #pragma unroll
        for (int w = 0; w < 8; w++) s += red[w];
        g_anchor[b * 64 + i] = s * 0.5f;
    }

    // ---- fused head: last block of the grid reduces and runs the MLP ----
    if (t == 0) {
        __threadfence();
        unsigned vdone = atomicAdd(&g_done, 1u);
        sflag = (vdone == (unsigned)(NP * BSZ - 1));
    }
    __syncthreads();
    if (sflag) {
        int bb = t >> 3, p = t & 7;
        float s = 0.f;
        #pragma unroll
        for (int m = 0; m < 8; m++) s += g_anchor[bb * 64 + p + 8 * m];
        s += __shfl_xor_sync(0xFFFFFFFFu, s, 1);
        s += __shfl_xor_sync(0xFFFFFFFFu, s, 2);
        s += __shfl_xor_sync(0xFFFFFFFFu, s, 4);
        if (p == 0) sbat[bb] = s;
        __syncthreads();
        float sv = sbat[bb] * (1.0f / 16777216.0f);   // / N^3 / N
        float acc = 0.f;
        #pragma unroll
        for (int m = 0; m < 4; m++) {
            int j = p + 8 * m;
            float x = sv * W1[j] + b1[j];
            float uu = 0.7978845608028654f * (x + 0.044715f * x * x * x);
            float h = 0.5f * x * (1.0f + tanhf(uu));
            acc += h * W2[j];
        }
        acc += __shfl_xor_sync(0xFFFFFFFFu, acc, 1);
        acc += __shfl_xor_sync(0xFFFFFFFFu, acc, 2);
        acc += __shfl_xor_sync(0xFFFFFFFFu, acc, 4);
        if (p == 0) out[bb] = acc + b2[0];
    }
}

// ---------------------------------------------------------------------------
extern "C" void kernel_launch(void* const* d_in, const int* in_sizes, int n_in,
                              void* d_out, int out_size)
{
    const float* pc  = (const float*)d_in[0];
    const float* Wq  = (const float*)d_in[1];
    const float* bq  = (const float*)d_in[2];
    const float* Wk1 = (const float*)d_in[3];
    const float* bk1 = (const float*)d_in[4];
    const float* Wk2 = (const float*)d_in[5];
    const float* bk2 = (const float*)d_in[6];
    const float* Wk3 = (const float*)d_in[7];
    const float* bk3 = (const float*)d_in[8];
    const float* W1  = (const float*)d_in[9];
    const float* b1  = (const float*)d_in[10];
    const float* W2  = (const float*)d_in[11];
    const float* b2  = (const float*)d_in[12];
    float* out = (float*)d_out;

    kA<<<BSZ, 256>>>(pc, Wq, bq, Wk1, bk1, Wk2, bk2, Wk3, bk3);
    kB<<<dim3(6, BSZ), 256>>>();
    kC<<<dim3(NP, BSZ), 256>>>(pc, W1, b1, W2, b2, out);
}

// round 8
// speedup vs baseline: 1.1204x; 1.1204x over previous
#include <cuda_runtime.h>
#include <cuda_bf16.h>
#include <cuda_fp16.h>

// ---------------------------------------------------------------------------
// Simplex4Net: B=32, N=64, D=64
//   kA: projections (+ zero completion counter); kB: six Gram mats * 0.0625
//   kC: main B*N^4 loop, ALL-f16 inner chain (HADD2 energies, tanh.f16x2,
//       HFMA2 det, f16 windowed accumulate, flush to f32 every 4 j) —
//       zero per-element f32<->f16 conversions. Gate split as before:
//       sigma(E)det^2 = 0.5 det^2 (closed form, f32) + 0.5 det^2 tanh(E/2).
//       Fused head: last block does mean + gelu MLP.
// ---------------------------------------------------------------------------

#define BSZ 32
#define NP  64
#define DD  64

__device__ float g_K[4][BSZ][NP * DD];
__device__ float g_E[6][BSZ][NP * NP];   // 0:(i,j) 1:(i,k) 2:(i,l) 3:(j,k) 4:(j,l) 5:(l,k)^T
__device__ float g_anchor[BSZ * NP];
__device__ unsigned g_done;

typedef unsigned long long ull;

__device__ __forceinline__ ull pk2(float lo, float hi) {
    ull r; asm("mov.b64 %0, {%1, %2};" : "=l"(r) : "f"(lo), "f"(hi)); return r;
}
__device__ __forceinline__ void upk2(ull v, float& lo, float& hi) {
    asm("mov.b64 {%0, %1}, %2;" : "=f"(lo), "=f"(hi) : "l"(v));
}
__device__ __forceinline__ ull add2(ull a, ull b) {
    ull r; asm("add.rn.f32x2 %0, %1, %2;" : "=l"(r) : "l"(a), "l"(b)); return r;
}
__device__ __forceinline__ __half2 tanh2h(__half2 x) {
    unsigned xu = *reinterpret_cast<unsigned*>(&x);
    unsigned yu;
    asm("tanh.approx.f16x2 %0, %1;" : "=r"(yu) : "r"(xu));
    return *reinterpret_cast<__half2*>(&yu);
}
__device__ __forceinline__ __half2 u2h(unsigned u) {
    return *reinterpret_cast<__half2*>(&u);
}

// ---------------------------------------------------------------------------
__global__ void kA(const float* __restrict__ pc,
                   const float* __restrict__ Wq,  const float* __restrict__ bq,
                   const float* __restrict__ Wk1, const float* __restrict__ bk1,
                   const float* __restrict__ Wk2, const float* __restrict__ bk2,
                   const float* __restrict__ Wk3, const float* __restrict__ bk3)
{
    int b = blockIdx.x;
    __shared__ float sp[NP * 3];
    __shared__ float sW[4][3 * DD];
    __shared__ float sb[4][DD];
    int t = threadIdx.x;
    if (b == 0 && t == 0) g_done = 0;
    if (t < 192) {
        sp[t]    = pc[b * 192 + t];
        sW[0][t] = Wq[t];
        sW[1][t] = Wk1[t];
        sW[2][t] = Wk2[t];
        sW[3][t] = Wk3[t];
    }
    if (t < 64) {
        sb[0][t] = bq[t]; sb[1][t] = bk1[t]; sb[2][t] = bk2[t]; sb[3][t] = bk3[t];
    }
    __syncthreads();
    for (int m = 0; m < 4; m++) {
        const float* W = sW[m];
        const float* bb = sb[m];
        for (int idx = t; idx < NP * DD; idx += 256) {
            int n = idx >> 6, d = idx & 63;
            float v = bb[d]
                    + sp[n * 3 + 0] * W[d]
                    + sp[n * 3 + 1] * W[64 + d]
                    + sp[n * 3 + 2] * W[128 + d];
            g_K[m][b][idx] = v;
        }
    }
}

// ---------------------------------------------------------------------------
__global__ void kB()
{
    int p = blockIdx.x, b = blockIdx.y;
    const int XI[6] = {0, 0, 0, 1, 1, 3};
    const int YI[6] = {1, 2, 3, 2, 3, 2};
    __shared__ float sX[NP][65];
    __shared__ float sY[NP][65];
    int t = threadIdx.x;
    const float* X = g_K[XI[p]][b];
    const float* Y = g_K[YI[p]][b];
    for (int idx = t; idx < NP * DD; idx += 256) {
        sX[idx >> 6][idx & 63] = X[idx];
        sY[idx >> 6][idx & 63] = Y[idx];
    }
    __syncthreads();
    for (int idx = t; idx < NP * NP; idx += 256) {
        int n = idx >> 6, m = idx & 63;
        float s = 0.f;
        #pragma unroll
        for (int d = 0; d < DD; d++)
            s = fmaf(sX[n][d], sY[m][d], s);
        g_E[p][b][idx] = s * 0.0625f;
    }
}

// ---------------------------------------------------------------------------
// Kernel C: grid=(i=64,b=32), 256 threads, occ-3 via smem pad.
// Thread = (k = t&63, l-quad per unit). All-f16 inner chain.
// ---------------------------------------------------------------------------
__global__ void __launch_bounds__(256, 3) kC(const float* __restrict__ pc,
                                             const float* __restrict__ W1,
                                             const float* __restrict__ b1,
                                             const float* __restrict__ W2,
                                             const float* __restrict__ b2,
                                             float* __restrict__ out)
{
    __shared__ __align__(16) __half2 SA2h[64 * 64];   // 16 KB  {a,a} per (j,k)
    __shared__ __align__(16) __half  SB4h[64 * 64];   // 8 KB   b per (j,l)
    __shared__ __align__(16) __half2 DJh[64][4];      // 2 KB   {x,x},{y,y},{z,z},pad
    __shared__ float4  dS[NP];                        // 1 KB
    __shared__ float   ekA[NP];
    __shared__ float   sS[6];
    __shared__ float   red[8];
    __shared__ float   sbat[BSZ];
    __shared__ int     sflag;
    __shared__ ull     PAD[3968];                     // ~31 KB -> total ~59 KB -> occ 3

    int i = blockIdx.x, b = blockIdx.y, t = threadIdx.x;
    if (pc == (const float*)1) ((volatile ull*)PAD)[0] = 1;   // keep PAD live

    const float* E0r = &g_E[0][b][i * 64];
    const float* E2r = &g_E[2][b][i * 64];
    const float* E3b = g_E[3][b];
    const float* E4b = g_E[4][b];

    for (int idx = t; idx < NP * NP; idx += 256) {
        int j = idx >> 6, c = idx & 63;
        float av = E3b[idx] + E0r[j];
        SA2h[(j << 6) + c] = __float2half2_rn(av);
        float bv = E4b[idx] + E2r[c];
        SB4h[(j << 6) + c] = __float2half_rn(bv);
    }
    if (t < 64) {
        ekA[t] = g_E[1][b][i * 64 + t];
        float ix = pc[b * 192 + i * 3 + 0];
        float iy = pc[b * 192 + i * 3 + 1];
        float iz = pc[b * 192 + i * 3 + 2];
        float dx = pc[b * 192 + t * 3 + 0] - ix;
        float dy = pc[b * 192 + t * 3 + 1] - iy;
        float dz = pc[b * 192 + t * 3 + 2] - iz;
        dS[t] = make_float4(dx, dy, dz, 0.f);
    }
    __syncthreads();
    if (t < 64) {
        float4 d = dS[t];
        DJh[t][0] = __float2half2_rn(d.x);
        DJh[t][1] = __float2half2_rn(d.y);
        DJh[t][2] = __float2half2_rn(d.z);
        DJh[t][3] = __float2half2_rn(0.f);
    } else if (t < 70) {
        int e = t - 64;
        int c1 = 0, c2 = 0;
        if (e == 1) { c1 = 1; c2 = 1; }
        if (e == 2) { c1 = 2; c2 = 2; }
        if (e == 3) { c1 = 0; c2 = 1; }
        if (e == 4) { c1 = 0; c2 = 2; }
        if (e == 5) { c1 = 1; c2 = 2; }
        float s = 0.f;
        for (int j = 0; j < 64; j++) {
            const float* dp = reinterpret_cast<const float*>(&dS[j]);
            s = fmaf(dp[c1], dp[c2], s);
        }
        sS[e] = s;
    }
    __syncthreads();

    const float* E5b = g_E[5][b];            // [l][k]
    ull accP = pk2(0.f, 0.f);
    ull accQ = pk2(0.f, 0.f);
    float qsum = 0.f;

    int k = t & 63;
    float4 dk = dS[k];
    float ekk = ekA[k];
    float Sxx = sS[0], Syy = sS[1], Szz = sS[2];
    float Sxy2 = 2.f * sS[3], Sxz2 = 2.f * sS[4], Syz2 = 2.f * sS[5];
    const __half2 hzero = __float2half2_rn(0.f);

    #pragma unroll 1
    for (int u = 0; u < 4; u++) {
        int lq = u * 4 + (t >> 6);
        int l0 = lq * 4;

        float4 dA = dS[l0 + 0];
        float4 dB = dS[l0 + 1];
        float4 dC = dS[l0 + 2];
        float4 dD = dS[l0 + 3];

        float cAx = dk.y * dA.z - dk.z * dA.y, cAy = dk.z * dA.x - dk.x * dA.z, cAz = dk.x * dA.y - dk.y * dA.x;
        float cBx = dk.y * dB.z - dk.z * dB.y, cBy = dk.z * dB.x - dk.x * dB.z, cBz = dk.x * dB.y - dk.y * dB.x;
        float cCx = dk.y * dC.z - dk.z * dC.y, cCy = dk.z * dC.x - dk.x * dC.z, cCz = dk.x * dC.y - dk.y * dC.x;
        float cDx = dk.y * dD.z - dk.z * dD.y, cDy = dk.z * dD.x - dk.x * dD.z, cDz = dk.x * dD.y - dk.y * dD.x;

        // closed-form ungated half (exact f32): c^T S c per l
        {
            float qA = cAx * (fmaf(Sxy2, cAy, fmaf(Sxz2, cAz, Sxx * cAx)))
                     + cAy * fmaf(Syz2, cAz, Syy * cAy) + cAz * cAz * Szz;
            float qB = cBx * (fmaf(Sxy2, cBy, fmaf(Sxz2, cBz, Sxx * cBx)))
                     + cBy * fmaf(Syz2, cBz, Syy * cBy) + cBz * cBz * Szz;
            float qC = cCx * (fmaf(Sxy2, cCy, fmaf(Sxz2, cCz, Sxx * cCx)))
                     + cCy * fmaf(Syz2, cCz, Syy * cCy) + cCz * cCz * Szz;
            float qD = cDx * (fmaf(Sxy2, cDy, fmaf(Sxz2, cDz, Sxx * cDx)))
                     + cDy * fmaf(Syz2, cDz, Syy * cDy) + cDz * cDz * Szz;
            qsum += (qA + qB) + (qC + qD);
        }

        // f16 cross products (packed over l pairs) — converted once per unit
        __half2 cx01 = __floats2half2_rn(cAx, cBx);
        __half2 cy01 = __floats2half2_rn(cAy, cBy);
        __half2 cz01 = __floats2half2_rn(cAz, cBz);
        __half2 cx23 = __floats2half2_rn(cCx, cDx);
        __half2 cy23 = __floats2half2_rn(cCy, cDy);
        __half2 cz23 = __floats2half2_rn(cCz, cDz);

        __half2 ecAh = __floats2half2_rn(ekk + E5b[(l0 + 0) * 64 + k], ekk + E5b[(l0 + 1) * 64 + k]);
        __half2 ecBh = __floats2half2_rn(ekk + E5b[(l0 + 2) * 64 + k], ekk + E5b[(l0 + 3) * 64 + k]);

        const __half* SBbase = SB4h + (lq << 2);
        __half2 winP = hzero, winQ = hzero;

        #pragma unroll 8
        for (int j = 0; j < 64; j++) {
            __half2 aa = SA2h[(j << 6) + k];                              // LDS.32
            uint2 bqv = *reinterpret_cast<const uint2*>(SBbase + (j << 6)); // LDS.64 bcast
            uint4 djv = *reinterpret_cast<const uint4*>(&DJh[j][0]);        // LDS.128 bcast

            __half2 b01 = u2h(bqv.x), b23 = u2h(bqv.y);
            __half2 e01 = __hadd2(__hadd2(aa, b01), ecAh);
            __half2 e23 = __hadd2(__hadd2(aa, b23), ecBh);
            __half2 t01 = tanh2h(e01);
            __half2 t23 = tanh2h(e23);

            __half2 xx = u2h(djv.x), yy = u2h(djv.y), zz = u2h(djv.z);
            __half2 d01 = __hfma2(cx01, xx, __hfma2(cy01, yy, __hmul2(cz01, zz)));
            __half2 d23 = __hfma2(cx23, xx, __hfma2(cy23, yy, __hmul2(cz23, zz)));

            winP = __hfma2(__hmul2(d01, d01), t01, winP);
            winQ = __hfma2(__hmul2(d23, d23), t23, winQ);

            if ((j & 3) == 3) {   // flush window (static under unroll 8)
                accP = add2(accP, pk2(__low2float(winP), __high2float(winP)));
                accQ = add2(accQ, pk2(__low2float(winQ), __high2float(winQ)));
                winP = hzero; winQ = hzero;
            }
        }
    }

    float a0, a1, b0_, b1_;
    upk2(accP, a0, a1); upk2(accQ, b0_, b1_);
    float v = ((a0 + a1) + (b0_ + b1_)) + qsum;
    #pragma unroll
    for (int off = 16; off > 0; off >>= 1)
        v += __shfl_xor_sync(0xFFFFFFFFu, v, off);
    if ((t & 31) == 0) red[t >> 5] = v;
    __syncthreads();
    if (t == 0) {
        float s = 0.f;
        #pragma unroll
        for (int w = 0; w < 8; w++) s += red[w];
        g_anchor[b * 64 + i] = s * 0.5f;
    }

    // ---- fused head: last finishing block reduces + runs the MLP ----
    if (t == 0) {
        __threadfence();
        unsigned vdone = atomicAdd(&g_done, 1u);
        sflag = (vdone == (unsigned)(NP * BSZ - 1));
    }
    __syncthreads();
    if (sflag) {
        int bb = t >> 3, p = t & 7;
        float s = 0.f;
        #pragma unroll
        for (int m = 0; m < 8; m++) s += g_anchor[bb * 64 + p + 8 * m];
        s += __shfl_xor_sync(0xFFFFFFFFu, s, 1);
        s += __shfl_xor_sync(0xFFFFFFFFu, s, 2);
        s += __shfl_xor_sync(0xFFFFFFFFu, s, 4);
        if (p == 0) sbat[bb] = s;
        __syncthreads();
        float sv = sbat[bb] * (1.0f / 16777216.0f);   // / N^3 / N
        float acc = 0.f;
        #pragma unroll
        for (int m = 0; m < 4; m++) {
            int j = p + 8 * m;
            float x = sv * W1[j] + b1[j];
            float uu = 0.7978845608028654f * (x + 0.044715f * x * x * x);
            float h = 0.5f * x * (1.0f + tanhf(uu));
            acc += h * W2[j];
        }
        acc += __shfl_xor_sync(0xFFFFFFFFu, acc, 1);
        acc += __shfl_xor_sync(0xFFFFFFFFu, acc, 2);
        acc += __shfl_xor_sync(0xFFFFFFFFu, acc, 4);
        if (p == 0) out[bb] = acc + b2[0];
    }
}

// ---------------------------------------------------------------------------
extern "C" void kernel_launch(void* const* d_in, const int* in_sizes, int n_in,
                              void* d_out, int out_size)
{
    const float* pc  = (const float*)d_in[0];
    const float* Wq  = (const float*)d_in[1];
    const float* bq  = (const float*)d_in[2];
    const float* Wk1 = (const float*)d_in[3];
    const float* bk1 = (const float*)d_in[4];
    const float* Wk2 = (const float*)d_in[5];
    const float* bk2 = (const float*)d_in[6];
    const float* Wk3 = (const float*)d_in[7];
    const float* bk3 = (const float*)d_in[8];
    const float* W1  = (const float*)d_in[9];
    const float* b1  = (const float*)d_in[10];
    const float* W2  = (const float*)d_in[11];
    const float* b2  = (const float*)d_in[12];
    float* out = (float*)d_out;

    kA<<<BSZ, 256>>>(pc, Wq, bq, Wk1, bk1, Wk2, bk2, Wk3, bk3);
    kB<<<dim3(6, BSZ), 256>>>();
    kC<<<dim3(NP, BSZ), 256>>>(pc, W1, b1, W2, b2, out);
}